// round 9
// baseline (speedup 1.0000x reference)
#include <cuda_runtime.h>
#include <cuda_fp16.h>

#define N_NODES 100000
#define N_EDGES 1600000
#define DIM 64
#define NITEMS (N_NODES * 4)                      // 400000 (dst,attr) buckets
#define SCAN_CHUNK 4096                           // 1024 thr x 4 items
#define NCH ((NITEMS + SCAN_CHUNK - 1) / SCAN_CHUNK)   // 98

// scratch (allocation-free: device globals; zero-initialized at module load)
__device__ float  g_h[(size_t)N_NODES * DIM];     // (1+eps)*x + agg
__device__ float  g_t[(size_t)N_NODES * DIM];     // h@W1 + b1
__device__ __half g_x16[(size_t)N_NODES * DIM];   // fp16 copy of x (gather path)
__device__ float  g_sum[DIM];
__device__ float  g_sq[DIM];
__device__ int    g_deg4[NITEMS];                 // invariant: zero at entry (agg resets)
__device__ int    g_off4[NITEMS];
__device__ int    g_cur4[NITEMS];
__device__ unsigned long long g_state[NCH];       // invariant: zero at entry (scatter resets)
__device__ int    g_es[N_EDGES];                  // src node id

#define PACK2(d, lo, hi)  asm("mov.b64 %0, {%1, %2};" : "=l"(d) : "f"(lo), "f"(hi))
#define UNPACK2(lo, hi, s) asm("mov.b64 {%0, %1}, %2;" : "=f"(lo), "=f"(hi) : "l"(s))
#define FMA2(acc, a, b)   asm("fma.rn.f32x2 %0, %1, %2, %0;" : "+l"(acc) : "l"(a), "l"(b))

// ---------------------------------------------------------------------------
// K0: prep — x -> fp16 (8 floats/thread) + histogram over (dst,attr).
// ---------------------------------------------------------------------------
__global__ void prep_kernel(const float* __restrict__ x, const int* __restrict__ ei,
                            const int* __restrict__ ea) {
    int i = blockIdx.x * 256 + threadIdx.x;
    if (i < N_NODES * DIM / 8) {
        float4 a = __ldg((const float4*)x + 2 * i);
        float4 b = __ldg((const float4*)x + 2 * i + 1);
        __half2 h0 = __floats2half2_rn(a.x, a.y);
        __half2 h1 = __floats2half2_rn(a.z, a.w);
        __half2 h2 = __floats2half2_rn(b.x, b.y);
        __half2 h3 = __floats2half2_rn(b.z, b.w);
        uint4 p;
        p.x = *(unsigned*)&h0; p.y = *(unsigned*)&h1;
        p.z = *(unsigned*)&h2; p.w = *(unsigned*)&h3;
        ((uint4*)g_x16)[i] = p;
    }
    if (i < N_EDGES / 4) {
        int4 d = ((const int4*)(ei + N_EDGES))[i];
        int4 a = ((const int4*)ea)[i];
        atomicAdd(&g_deg4[d.x * 4 + a.x], 1);
        atomicAdd(&g_deg4[d.y * 4 + a.y], 1);
        atomicAdd(&g_deg4[d.z * 4 + a.z], 1);
        atomicAdd(&g_deg4[d.w * 4 + a.w], 1);
    }
}

// ---------------------------------------------------------------------------
// K1: single-launch scan over 400K bucket counts (4 items/thread).
// Each block publishes its total; polls all predecessors in parallel.
// Block 0 zeroes BN accumulators. 98 blocks <= 148 SMs.
// ---------------------------------------------------------------------------
__global__ void scan_kernel() {
    __shared__ int warp_sums[32];
    __shared__ int s_tot[128];
    int b = blockIdx.x;
    int i0 = b * SCAN_CHUNK + threadIdx.x * 4;

    int4 d4 = make_int4(0, 0, 0, 0);
    if (i0 + 3 < NITEMS) d4 = *(const int4*)(g_deg4 + i0);
    else if (i0 < NITEMS) {
        d4.x = g_deg4[i0];
        if (i0 + 1 < NITEMS) d4.y = g_deg4[i0 + 1];
        if (i0 + 2 < NITEMS) d4.z = g_deg4[i0 + 2];
    }
    int dsum = d4.x + d4.y + d4.z + d4.w;

    int v = dsum;
    int lane = threadIdx.x & 31, wid = threadIdx.x >> 5;
    #pragma unroll
    for (int o = 1; o < 32; o <<= 1) {
        int t = __shfl_up_sync(0xFFFFFFFFu, v, o);
        if (lane >= o) v += t;
    }
    if (lane == 31) warp_sums[wid] = v;
    __syncthreads();
    if (wid == 0) {
        int s = warp_sums[lane];
        #pragma unroll
        for (int o = 1; o < 32; o <<= 1) {
            int t = __shfl_up_sync(0xFFFFFFFFu, s, o);
            if (lane >= o) s += t;
        }
        warp_sums[lane] = s;
    }
    __syncthreads();
    int incl  = v + (wid > 0 ? warp_sums[wid - 1] : 0);
    int total = warp_sums[31];

    if (threadIdx.x == 0)
        atomicExch(&g_state[b], ((unsigned long long)(unsigned)total << 32) | 1ull);

    if (b == 0 && threadIdx.x < DIM) { g_sum[threadIdx.x] = 0.0f; g_sq[threadIdx.x] = 0.0f; }

    if (threadIdx.x < 128) s_tot[threadIdx.x] = 0;
    __syncthreads();
    if ((int)threadIdx.x < b) {
        unsigned long long st;
        do { st = *(volatile unsigned long long*)&g_state[threadIdx.x]; } while (!(st & 1ull));
        s_tot[threadIdx.x] = (int)(st >> 32);
    }
    __syncthreads();
    if (threadIdx.x < 64) s_tot[threadIdx.x] += s_tot[threadIdx.x + 64];
    __syncthreads();
    if (threadIdx.x < 32) {
        int s = s_tot[threadIdx.x] + s_tot[threadIdx.x + 32];
        #pragma unroll
        for (int o = 16; o > 0; o >>= 1) s += __shfl_down_sync(0xFFFFFFFFu, s, o);
        if (threadIdx.x == 0) s_tot[0] = s;
    }
    __syncthreads();

    int ex = s_tot[0] + incl - dsum;
    if (i0 + 3 < NITEMS) {
        int4 o4 = make_int4(ex, ex + d4.x, ex + d4.x + d4.y, ex + d4.x + d4.y + d4.z);
        *(int4*)(g_off4 + i0) = o4;
        *(int4*)(g_cur4 + i0) = o4;
    } else if (i0 < NITEMS) {
        int r = ex;
        g_off4[i0] = r; g_cur4[i0] = r; r += d4.x;
        if (i0 + 1 < NITEMS) { g_off4[i0 + 1] = r; g_cur4[i0 + 1] = r; r += d4.y; }
        if (i0 + 2 < NITEMS) { g_off4[i0 + 2] = r; g_cur4[i0 + 2] = r; }
    }
}

// ---------------------------------------------------------------------------
// K2: scatter src into (dst,attr) buckets — 4 edges/thread; blk0 resets state
// ---------------------------------------------------------------------------
__global__ void scatter_kernel(const int* __restrict__ ei, const int* __restrict__ ea) {
    if (blockIdx.x == 0 && threadIdx.x < NCH) g_state[threadIdx.x] = 0ull;
    int i = blockIdx.x * 256 + threadIdx.x;       // int4 index
    if (i >= N_EDGES / 4) return;
    int4 s = ((const int4*)ei)[i];
    int4 d = ((const int4*)(ei + N_EDGES))[i];
    int4 a = ((const int4*)ea)[i];
    int p0 = atomicAdd(&g_cur4[d.x * 4 + a.x], 1);
    int p1 = atomicAdd(&g_cur4[d.y * 4 + a.y], 1);
    int p2 = atomicAdd(&g_cur4[d.z * 4 + a.z], 1);
    int p3 = atomicAdd(&g_cur4[d.w * 4 + a.w], 1);
    g_es[p0] = s.x;
    g_es[p1] = s.y;
    g_es[p2] = s.z;
    g_es[p3] = s.w;
}

// ---------------------------------------------------------------------------
// K3: aggregate — per node, 4 attr buckets; emb loaded once per bucket into
// registers; per edge: 1 index LDG + 1 LDG.128 fp16 gather + fp32 relu-add.
// 8 lanes/node. Gather table = 12.8MB (L2-resident).
// ---------------------------------------------------------------------------
__global__ void __launch_bounds__(256)
agg_kernel(const float* __restrict__ x, const float* __restrict__ emb,
           const float* __restrict__ eps) {
    __shared__ float s_emb[4 * DIM];
    s_emb[threadIdx.x] = emb[threadIdx.x];
    __syncthreads();

    int gt = blockIdx.x * 256 + threadIdx.x;
    int n = gt >> 3;
    int lane = gt & 7;
    if (n >= N_NODES) return;

    int4 off4 = *(const int4*)(g_off4 + n * 4);
    int4 deg4 = *(const int4*)(g_deg4 + n * 4);
    if (lane == 0) *(int4*)(g_deg4 + n * 4) = make_int4(0, 0, 0, 0);  // restore invariant

    float s = 1.0f + __ldg(eps);
    const float4* xp = (const float4*)(x + (size_t)n * DIM + lane * 8);
    float4 accA = __ldg(xp);
    float4 accB = __ldg(xp + 1);
    accA.x *= s; accA.y *= s; accA.z *= s; accA.w *= s;
    accB.x *= s; accB.y *= s; accB.z *= s; accB.w *= s;

    const uint4* xb = (const uint4*)g_x16;        // 8 uint4 per 64-half row

    #pragma unroll
    for (int a = 0; a < 4; a++) {
        int off = (a == 0) ? off4.x : (a == 1) ? off4.y : (a == 2) ? off4.z : off4.w;
        int deg = (a == 0) ? deg4.x : (a == 1) ? deg4.y : (a == 2) ? deg4.z : deg4.w;
        if (deg == 0) continue;
        const float4* ep = (const float4*)(s_emb + a * DIM + lane * 8);
        float4 ea = ep[0], eb = ep[1];

        int j = 0;
        for (; j + 4 <= deg; j += 4) {
            int p0 = __ldg(g_es + off + j);
            int p1 = __ldg(g_es + off + j + 1);
            int p2 = __ldg(g_es + off + j + 2);
            int p3 = __ldg(g_es + off + j + 3);
            uint4 r0 = __ldg(xb + (size_t)p0 * 8 + lane);
            uint4 r1 = __ldg(xb + (size_t)p1 * 8 + lane);
            uint4 r2 = __ldg(xb + (size_t)p2 * 8 + lane);
            uint4 r3 = __ldg(xb + (size_t)p3 * 8 + lane);
            {
                float2 f0 = __half22float2(*(__half2*)&r0.x);
                float2 f1 = __half22float2(*(__half2*)&r0.y);
                float2 f2 = __half22float2(*(__half2*)&r0.z);
                float2 f3 = __half22float2(*(__half2*)&r0.w);
                accA.x += fmaxf(f0.x + ea.x, 0.0f); accA.y += fmaxf(f0.y + ea.y, 0.0f);
                accA.z += fmaxf(f1.x + ea.z, 0.0f); accA.w += fmaxf(f1.y + ea.w, 0.0f);
                accB.x += fmaxf(f2.x + eb.x, 0.0f); accB.y += fmaxf(f2.y + eb.y, 0.0f);
                accB.z += fmaxf(f3.x + eb.z, 0.0f); accB.w += fmaxf(f3.y + eb.w, 0.0f);
            }
            {
                float2 f0 = __half22float2(*(__half2*)&r1.x);
                float2 f1 = __half22float2(*(__half2*)&r1.y);
                float2 f2 = __half22float2(*(__half2*)&r1.z);
                float2 f3 = __half22float2(*(__half2*)&r1.w);
                accA.x += fmaxf(f0.x + ea.x, 0.0f); accA.y += fmaxf(f0.y + ea.y, 0.0f);
                accA.z += fmaxf(f1.x + ea.z, 0.0f); accA.w += fmaxf(f1.y + ea.w, 0.0f);
                accB.x += fmaxf(f2.x + eb.x, 0.0f); accB.y += fmaxf(f2.y + eb.y, 0.0f);
                accB.z += fmaxf(f3.x + eb.z, 0.0f); accB.w += fmaxf(f3.y + eb.w, 0.0f);
            }
            {
                float2 f0 = __half22float2(*(__half2*)&r2.x);
                float2 f1 = __half22float2(*(__half2*)&r2.y);
                float2 f2 = __half22float2(*(__half2*)&r2.z);
                float2 f3 = __half22float2(*(__half2*)&r2.w);
                accA.x += fmaxf(f0.x + ea.x, 0.0f); accA.y += fmaxf(f0.y + ea.y, 0.0f);
                accA.z += fmaxf(f1.x + ea.z, 0.0f); accA.w += fmaxf(f1.y + ea.w, 0.0f);
                accB.x += fmaxf(f2.x + eb.x, 0.0f); accB.y += fmaxf(f2.y + eb.y, 0.0f);
                accB.z += fmaxf(f3.x + eb.z, 0.0f); accB.w += fmaxf(f3.y + eb.w, 0.0f);
            }
            {
                float2 f0 = __half22float2(*(__half2*)&r3.x);
                float2 f1 = __half22float2(*(__half2*)&r3.y);
                float2 f2 = __half22float2(*(__half2*)&r3.z);
                float2 f3 = __half22float2(*(__half2*)&r3.w);
                accA.x += fmaxf(f0.x + ea.x, 0.0f); accA.y += fmaxf(f0.y + ea.y, 0.0f);
                accA.z += fmaxf(f1.x + ea.z, 0.0f); accA.w += fmaxf(f1.y + ea.w, 0.0f);
                accB.x += fmaxf(f2.x + eb.x, 0.0f); accB.y += fmaxf(f2.y + eb.y, 0.0f);
                accB.z += fmaxf(f3.x + eb.z, 0.0f); accB.w += fmaxf(f3.y + eb.w, 0.0f);
            }
        }
        for (; j < deg; j++) {
            int p0 = __ldg(g_es + off + j);
            uint4 r0 = __ldg(xb + (size_t)p0 * 8 + lane);
            float2 f0 = __half22float2(*(__half2*)&r0.x);
            float2 f1 = __half22float2(*(__half2*)&r0.y);
            float2 f2 = __half22float2(*(__half2*)&r0.z);
            float2 f3 = __half22float2(*(__half2*)&r0.w);
            accA.x += fmaxf(f0.x + ea.x, 0.0f); accA.y += fmaxf(f0.y + ea.y, 0.0f);
            accA.z += fmaxf(f1.x + ea.z, 0.0f); accA.w += fmaxf(f1.y + ea.w, 0.0f);
            accB.x += fmaxf(f2.x + eb.x, 0.0f); accB.y += fmaxf(f2.y + eb.y, 0.0f);
            accB.z += fmaxf(f3.x + eb.z, 0.0f); accB.w += fmaxf(f3.y + eb.w, 0.0f);
        }
    }

    float4* hp = (float4*)(g_h + (size_t)n * DIM + lane * 8);
    hp[0] = accA;
    hp[1] = accB;
}

// ---------------------------------------------------------------------------
// K4/K5: 128x64 tile GEMM, 8x8 per thread, fma.rn.f32x2 inner loop.
// MODE 0: t = g_h @ W1 + b1, write g_t, accumulate column sum/sumsq
// MODE 1: out = relu(t*A + B) @ W2 + b2, BN affine computed from g_sum/g_sq
// ---------------------------------------------------------------------------
#define TILE_R    128
#define IN_STRIDE 132
#define SMEM_FLOATS (DIM * DIM + DIM * IN_STRIDE + 2 * DIM)   // 12672

template <int MODE>
__global__ void gemm_kernel(const float* __restrict__ W, const float* __restrict__ bias,
                            const float* __restrict__ gamma, const float* __restrict__ beta,
                            float* __restrict__ out_ext) {
    extern __shared__ float sm[];
    float* sW   = sm;                               // [64][64]
    float* sIn  = sm + DIM * DIM;                   // [64][IN_STRIDE] k-major
    float* sAff = sm + DIM * DIM + DIM * IN_STRIDE; // [2][64]

    const float* in  = (MODE == 0) ? g_h : g_t;
    float*       out = (MODE == 0) ? g_t : out_ext;

    int t  = threadIdx.x;            // 128 threads
    int r0 = blockIdx.x * TILE_R;

    #pragma unroll
    for (int i = 0; i < 8; i++)
        ((float4*)sW)[t + i * 128] = ((const float4*)W)[t + i * 128];

    if (MODE == 1) {
        if (t < DIM) {
            const float inv = 1.0f / (float)N_NODES;
            float mu  = g_sum[t] * inv;
            float var = g_sq[t] * inv - mu * mu;
            float a   = gamma[t] * rsqrtf(var + 1e-5f);
            sAff[t]       = a;
            sAff[DIM + t] = fmaf(-mu, a, beta[t]);
        }
        __syncthreads();
    }

    {
        int row = r0 + t;
        bool valid = row < N_NODES;
        const float4* rp = (const float4*)(in + (size_t)row * DIM);
        #pragma unroll
        for (int q = 0; q < 16; q++) {
            float4 v = valid ? __ldg(rp + q) : make_float4(0.f, 0.f, 0.f, 0.f);
            int k0 = q * 4;
            if (MODE == 1) {
                v.x = fmaxf(fmaf(v.x, sAff[k0 + 0], sAff[DIM + k0 + 0]), 0.0f);
                v.y = fmaxf(fmaf(v.y, sAff[k0 + 1], sAff[DIM + k0 + 1]), 0.0f);
                v.z = fmaxf(fmaf(v.z, sAff[k0 + 2], sAff[DIM + k0 + 2]), 0.0f);
                v.w = fmaxf(fmaf(v.w, sAff[k0 + 3], sAff[DIM + k0 + 3]), 0.0f);
            }
            sIn[(k0 + 0) * IN_STRIDE + t] = v.x;
            sIn[(k0 + 1) * IN_STRIDE + t] = v.y;
            sIn[(k0 + 2) * IN_STRIDE + t] = v.z;
            sIn[(k0 + 3) * IN_STRIDE + t] = v.w;
        }
    }
    __syncthreads();

    int rg = t >> 3;  // 0..15
    int cg = t & 7;   // 0..7

    unsigned long long acc2[8][4];
    #pragma unroll
    for (int i = 0; i < 8; i++)
        #pragma unroll
        for (int jp = 0; jp < 4; jp++) acc2[i][jp] = 0ull;

    #pragma unroll 2
    for (int k = 0; k < 64; k++) {
        float4 a0 = *(const float4*)(sIn + k * IN_STRIDE + rg * 8);
        float4 a1 = *(const float4*)(sIn + k * IN_STRIDE + rg * 8 + 4);
        float4 w0 = *(const float4*)(sW  + k * DIM + cg * 8);
        float4 w1 = *(const float4*)(sW  + k * DIM + cg * 8 + 4);
        unsigned long long w2[4];
        PACK2(w2[0], w0.x, w0.y);
        PACK2(w2[1], w0.z, w0.w);
        PACK2(w2[2], w1.x, w1.y);
        PACK2(w2[3], w1.z, w1.w);
        float av[8] = {a0.x, a0.y, a0.z, a0.w, a1.x, a1.y, a1.z, a1.w};
        #pragma unroll
        for (int i = 0; i < 8; i++) {
            unsigned long long ai;
            PACK2(ai, av[i], av[i]);
            #pragma unroll
            for (int jp = 0; jp < 4; jp++)
                FMA2(acc2[i][jp], ai, w2[jp]);
        }
    }

    float bs[8];
    #pragma unroll
    for (int j = 0; j < 8; j++) bs[j] = bias[cg * 8 + j];

    float csum[8], csq[8];
    #pragma unroll
    for (int j = 0; j < 8; j++) { csum[j] = 0.0f; csq[j] = 0.0f; }

    #pragma unroll
    for (int i = 0; i < 8; i++) {
        int row = r0 + rg * 8 + i;
        if (row < N_NODES) {
            float v[8];
            #pragma unroll
            for (int jp = 0; jp < 4; jp++) {
                float lo, hi;
                UNPACK2(lo, hi, acc2[i][jp]);
                v[2 * jp]     = lo + bs[2 * jp];
                v[2 * jp + 1] = hi + bs[2 * jp + 1];
            }
            if (MODE == 0) {
                #pragma unroll
                for (int j = 0; j < 8; j++) { csum[j] += v[j]; csq[j] += v[j] * v[j]; }
            }
            *(float4*)(out + (size_t)row * DIM + cg * 8)     = make_float4(v[0], v[1], v[2], v[3]);
            *(float4*)(out + (size_t)row * DIM + cg * 8 + 4) = make_float4(v[4], v[5], v[6], v[7]);
        }
    }

    if (MODE == 0) {
        __syncthreads();
        float* red = sIn;
        #pragma unroll
        for (int j = 0; j < 8; j++) {
            red[rg * 64 + cg * 8 + j]        = csum[j];
            red[(16 + rg) * 64 + cg * 8 + j] = csq[j];
        }
        __syncthreads();
        if (t < 64) {
            float s = 0.0f;
            #pragma unroll
            for (int g = 0; g < 16; g++) s += red[g * 64 + t];
            atomicAdd(&g_sum[t], s);
        } else {
            int c = t - 64;
            float s = 0.0f;
            #pragma unroll
            for (int g = 0; g < 16; g++) s += red[(16 + g) * 64 + c];
            atomicAdd(&g_sq[c], s);
        }
    }
}

// ---------------------------------------------------------------------------
extern "C" void kernel_launch(void* const* d_in, const int* in_sizes, int n_in,
                              void* d_out, int out_size) {
    const float* x     = (const float*)d_in[0];
    const float* emb   = (const float*)d_in[1];
    const float* eps   = (const float*)d_in[2];
    const float* W1    = (const float*)d_in[3];
    const float* b1    = (const float*)d_in[4];
    const float* gamma = (const float*)d_in[5];
    const float* beta  = (const float*)d_in[6];
    const float* W2    = (const float*)d_in[7];
    const float* b2    = (const float*)d_in[8];
    const int*   ei    = (const int*)d_in[9];
    const int*   ea    = (const int*)d_in[10];
    float*       out   = (float*)d_out;

    const int smem_bytes = SMEM_FLOATS * 4;  // 50688 > 48K: opt in
    cudaFuncSetAttribute(gemm_kernel<0>, cudaFuncAttributeMaxDynamicSharedMemorySize, smem_bytes);
    cudaFuncSetAttribute(gemm_kernel<1>, cudaFuncAttributeMaxDynamicSharedMemorySize, smem_bytes);

    prep_kernel<<<(N_NODES * DIM / 8 + 255) / 256, 256>>>(x, ei, ea);   // 3125 blocks
    scan_kernel<<<NCH, 1024>>>();
    scatter_kernel<<<(N_EDGES / 4 + 255) / 256, 256>>>(ei, ea);         // 1563 blocks
    agg_kernel<<<(N_NODES * 8 + 255) / 256, 256>>>(x, emb, eps);        // 3125 blocks
    const int gblocks = (N_NODES + TILE_R - 1) / TILE_R;                // 782
    gemm_kernel<0><<<gblocks, 128, smem_bytes>>>(W1, b1, nullptr, nullptr, nullptr);
    gemm_kernel<1><<<gblocks, 128, smem_bytes>>>(W2, b2, gamma, beta, out);
}

// round 10
// speedup vs baseline: 1.0783x; 1.0783x over previous
#include <cuda_runtime.h>
#include <cuda_fp16.h>

#define N_NODES 100000
#define N_EDGES 1600000
#define DIM 64
#define SCAN_CHUNK 1024
#define NCH ((N_NODES + SCAN_CHUNK - 1) / SCAN_CHUNK)   // 98

// scratch (allocation-free: device globals; zero-initialized at module load)
__device__ float  g_h[(size_t)N_NODES * DIM];   // (1+eps)*x + agg
__device__ float  g_t[(size_t)N_NODES * DIM];   // h@W1 + b1
__device__ __half g_x16[(size_t)N_NODES * DIM]; // fp16 copy of x (gather path)
__device__ float  g_sum[DIM];
__device__ float  g_sq[DIM];
__device__ int    g_deg[N_NODES];               // invariant: zero at entry (agg resets)
__device__ int    g_off[N_NODES];
__device__ int    g_cur[N_NODES];
__device__ unsigned long long g_state[NCH];     // invariant: zero at entry (scatter resets)
__device__ unsigned g_es[N_EDGES];              // (attr<<28) | src

#define PACK2(d, lo, hi)  asm("mov.b64 %0, {%1, %2};" : "=l"(d) : "f"(lo), "f"(hi))
#define UNPACK2(lo, hi, s) asm("mov.b64 {%0, %1}, %2;" : "=f"(lo), "=f"(hi) : "l"(s))
#define FMA2(acc, a, b)   asm("fma.rn.f32x2 %0, %1, %2, %0;" : "+l"(acc) : "l"(a), "l"(b))

// ---------------------------------------------------------------------------
// K0: prep (x -> fp16, 8 floats/thread) + histogram of dst (4 edges/thread).
// ---------------------------------------------------------------------------
__global__ void prephist_kernel(const float* __restrict__ x, const int* __restrict__ ei) {
    int i = blockIdx.x * 256 + threadIdx.x;
    if (i < N_NODES * DIM / 8) {
        float4 a = __ldg((const float4*)x + 2 * i);
        float4 b = __ldg((const float4*)x + 2 * i + 1);
        __half2 h0 = __floats2half2_rn(a.x, a.y);
        __half2 h1 = __floats2half2_rn(a.z, a.w);
        __half2 h2 = __floats2half2_rn(b.x, b.y);
        __half2 h3 = __floats2half2_rn(b.z, b.w);
        uint4 p;
        p.x = *(unsigned*)&h0; p.y = *(unsigned*)&h1;
        p.z = *(unsigned*)&h2; p.w = *(unsigned*)&h3;
        ((uint4*)g_x16)[i] = p;
    }
    if (i < N_EDGES / 4) {
        int4 d = ((const int4*)(ei + N_EDGES))[i];
        atomicAdd(&g_deg[d.x], 1);
        atomicAdd(&g_deg[d.y], 1);
        atomicAdd(&g_deg[d.z], 1);
        atomicAdd(&g_deg[d.w], 1);
    }
}

// ---------------------------------------------------------------------------
// K1: single-launch scan; block publishes total, polls predecessors in
// parallel (one hop). Block 0 zeroes BN accumulators. 98 blocks resident.
// ---------------------------------------------------------------------------
__global__ void scan_kernel() {
    __shared__ int warp_sums[32];
    __shared__ int s_tot[128];
    int b = blockIdx.x;
    int idx = b * SCAN_CHUNK + threadIdx.x;
    int d = (idx < N_NODES) ? g_deg[idx] : 0;

    int v = d;
    int lane = threadIdx.x & 31, wid = threadIdx.x >> 5;
    #pragma unroll
    for (int o = 1; o < 32; o <<= 1) {
        int t = __shfl_up_sync(0xFFFFFFFFu, v, o);
        if (lane >= o) v += t;
    }
    if (lane == 31) warp_sums[wid] = v;
    __syncthreads();
    if (wid == 0) {
        int s = warp_sums[lane];
        #pragma unroll
        for (int o = 1; o < 32; o <<= 1) {
            int t = __shfl_up_sync(0xFFFFFFFFu, s, o);
            if (lane >= o) s += t;
        }
        warp_sums[lane] = s;
    }
    __syncthreads();
    int incl  = v + (wid > 0 ? warp_sums[wid - 1] : 0);
    int total = warp_sums[31];

    if (threadIdx.x == 0)
        atomicExch(&g_state[b], ((unsigned long long)(unsigned)total << 32) | 1ull);

    if (b == 0 && threadIdx.x < DIM) { g_sum[threadIdx.x] = 0.0f; g_sq[threadIdx.x] = 0.0f; }

    if (threadIdx.x < 128) s_tot[threadIdx.x] = 0;
    __syncthreads();
    if ((int)threadIdx.x < b) {
        unsigned long long st;
        do { st = *(volatile unsigned long long*)&g_state[threadIdx.x]; } while (!(st & 1ull));
        s_tot[threadIdx.x] = (int)(st >> 32);
    }
    __syncthreads();
    if (threadIdx.x < 64) s_tot[threadIdx.x] += s_tot[threadIdx.x + 64];
    __syncthreads();
    if (threadIdx.x < 32) {
        int s = s_tot[threadIdx.x] + s_tot[threadIdx.x + 32];
        #pragma unroll
        for (int o = 16; o > 0; o >>= 1) s += __shfl_down_sync(0xFFFFFFFFu, s, o);
        if (threadIdx.x == 0) s_tot[0] = s;
    }
    __syncthreads();
    int ex = s_tot[0] + incl - d;
    if (idx < N_NODES) { g_off[idx] = ex; g_cur[idx] = ex; }
}

// ---------------------------------------------------------------------------
// K2: scatter packed (attr,src) — 4 edges/thread; blk0 resets g_state
// ---------------------------------------------------------------------------
__global__ void scatter_kernel(const int* __restrict__ ei, const int* __restrict__ ea) {
    if (blockIdx.x == 0 && threadIdx.x < NCH) g_state[threadIdx.x] = 0ull;
    int i = blockIdx.x * 256 + threadIdx.x;       // int4 index
    if (i >= N_EDGES / 4) return;
    int4 s = ((const int4*)ei)[i];
    int4 d = ((const int4*)(ei + N_EDGES))[i];
    int4 a = ((const int4*)ea)[i];
    int p0 = atomicAdd(&g_cur[d.x], 1);
    int p1 = atomicAdd(&g_cur[d.y], 1);
    int p2 = atomicAdd(&g_cur[d.z], 1);
    int p3 = atomicAdd(&g_cur[d.w], 1);
    g_es[p0] = (unsigned)s.x | ((unsigned)a.x << 28);
    g_es[p1] = (unsigned)s.y | ((unsigned)a.y << 28);
    g_es[p2] = (unsigned)s.z | ((unsigned)a.z << 28);
    g_es[p3] = (unsigned)s.w | ((unsigned)a.w << 28);
}

// ---------------------------------------------------------------------------
// K3: aggregate — 8 lanes/node. Per edge: 1 index LDG + 1 LDG.128 fp16 gather
// + 1 LDS.128 fp16 emb + HADD2/HMAX2 relu; fp16 accumulate per unroll-4
// block, converted to fp32 once per block. Self term exact fp32.
// ---------------------------------------------------------------------------
__global__ void __launch_bounds__(256)
agg_kernel(const float* __restrict__ x, const float* __restrict__ emb,
           const float* __restrict__ eps) {
    __shared__ __align__(16) __half s_emb16[4 * DIM];
    s_emb16[threadIdx.x] = __float2half(emb[threadIdx.x]);   // 256 == 4*64
    __syncthreads();

    int gt = blockIdx.x * 256 + threadIdx.x;
    int n = gt >> 3;
    int lane = gt & 7;
    if (n >= N_NODES) return;

    int off = g_off[n];
    int deg = g_deg[n];
    if (lane == 0) g_deg[n] = 0;              // restore invariant for next run
    float s = 1.0f + __ldg(eps);

    const float4* xp = (const float4*)(x + (size_t)n * DIM + lane * 8);
    float4 accA = __ldg(xp);
    float4 accB = __ldg(xp + 1);
    accA.x *= s; accA.y *= s; accA.z *= s; accA.w *= s;
    accB.x *= s; accB.y *= s; accB.z *= s; accB.w *= s;

    const uint4* xb = (const uint4*)g_x16;          // 8 uint4 per 64-half row
    const uint4* eb = (const uint4*)s_emb16;        // 8 uint4 per attr row
    const __half2 zero2 = __float2half2_rn(0.0f);

    int j = 0;
    for (; j + 4 <= deg; j += 4) {
        unsigned p0 = __ldg(g_es + off + j);
        unsigned p1 = __ldg(g_es + off + j + 1);
        unsigned p2 = __ldg(g_es + off + j + 2);
        unsigned p3 = __ldg(g_es + off + j + 3);
        uint4 r0 = __ldg(xb + (size_t)(p0 & 0x0FFFFFFFu) * 8 + lane);
        uint4 r1 = __ldg(xb + (size_t)(p1 & 0x0FFFFFFFu) * 8 + lane);
        uint4 r2 = __ldg(xb + (size_t)(p2 & 0x0FFFFFFFu) * 8 + lane);
        uint4 r3 = __ldg(xb + (size_t)(p3 & 0x0FFFFFFFu) * 8 + lane);
        uint4 e0 = eb[(p0 >> 28) * 8 + lane];
        uint4 e1 = eb[(p1 >> 28) * 8 + lane];
        uint4 e2 = eb[(p2 >> 28) * 8 + lane];
        uint4 e3 = eb[(p3 >> 28) * 8 + lane];

        __half2 a16_0, a16_1, a16_2, a16_3;
        a16_0 = __hmax2(__hadd2(*(__half2*)&r0.x, *(__half2*)&e0.x), zero2);
        a16_1 = __hmax2(__hadd2(*(__half2*)&r0.y, *(__half2*)&e0.y), zero2);
        a16_2 = __hmax2(__hadd2(*(__half2*)&r0.z, *(__half2*)&e0.z), zero2);
        a16_3 = __hmax2(__hadd2(*(__half2*)&r0.w, *(__half2*)&e0.w), zero2);
        a16_0 = __hadd2(a16_0, __hmax2(__hadd2(*(__half2*)&r1.x, *(__half2*)&e1.x), zero2));
        a16_1 = __hadd2(a16_1, __hmax2(__hadd2(*(__half2*)&r1.y, *(__half2*)&e1.y), zero2));
        a16_2 = __hadd2(a16_2, __hmax2(__hadd2(*(__half2*)&r1.z, *(__half2*)&e1.z), zero2));
        a16_3 = __hadd2(a16_3, __hmax2(__hadd2(*(__half2*)&r1.w, *(__half2*)&e1.w), zero2));
        a16_0 = __hadd2(a16_0, __hmax2(__hadd2(*(__half2*)&r2.x, *(__half2*)&e2.x), zero2));
        a16_1 = __hadd2(a16_1, __hmax2(__hadd2(*(__half2*)&r2.y, *(__half2*)&e2.y), zero2));
        a16_2 = __hadd2(a16_2, __hmax2(__hadd2(*(__half2*)&r2.z, *(__half2*)&e2.z), zero2));
        a16_3 = __hadd2(a16_3, __hmax2(__hadd2(*(__half2*)&r2.w, *(__half2*)&e2.w), zero2));
        a16_0 = __hadd2(a16_0, __hmax2(__hadd2(*(__half2*)&r3.x, *(__half2*)&e3.x), zero2));
        a16_1 = __hadd2(a16_1, __hmax2(__hadd2(*(__half2*)&r3.y, *(__half2*)&e3.y), zero2));
        a16_2 = __hadd2(a16_2, __hmax2(__hadd2(*(__half2*)&r3.z, *(__half2*)&e3.z), zero2));
        a16_3 = __hadd2(a16_3, __hmax2(__hadd2(*(__half2*)&r3.w, *(__half2*)&e3.w), zero2));

        float2 f0 = __half22float2(a16_0);
        float2 f1 = __half22float2(a16_1);
        float2 f2 = __half22float2(a16_2);
        float2 f3 = __half22float2(a16_3);
        accA.x += f0.x; accA.y += f0.y; accA.z += f1.x; accA.w += f1.y;
        accB.x += f2.x; accB.y += f2.y; accB.z += f3.x; accB.w += f3.y;
    }
    for (; j < deg; j++) {
        unsigned p0 = __ldg(g_es + off + j);
        uint4 r0 = __ldg(xb + (size_t)(p0 & 0x0FFFFFFFu) * 8 + lane);
        uint4 e0 = eb[(p0 >> 28) * 8 + lane];
        __half2 m0 = __hmax2(__hadd2(*(__half2*)&r0.x, *(__half2*)&e0.x), zero2);
        __half2 m1 = __hmax2(__hadd2(*(__half2*)&r0.y, *(__half2*)&e0.y), zero2);
        __half2 m2 = __hmax2(__hadd2(*(__half2*)&r0.z, *(__half2*)&e0.z), zero2);
        __half2 m3 = __hmax2(__hadd2(*(__half2*)&r0.w, *(__half2*)&e0.w), zero2);
        float2 f0 = __half22float2(m0);
        float2 f1 = __half22float2(m1);
        float2 f2 = __half22float2(m2);
        float2 f3 = __half22float2(m3);
        accA.x += f0.x; accA.y += f0.y; accA.z += f1.x; accA.w += f1.y;
        accB.x += f2.x; accB.y += f2.y; accB.z += f3.x; accB.w += f3.y;
    }

    float4* hp = (float4*)(g_h + (size_t)n * DIM + lane * 8);
    hp[0] = accA;
    hp[1] = accB;
}

// ---------------------------------------------------------------------------
// K4/K5: 128x64 tile GEMM, 8x8 per thread, fma.rn.f32x2 inner loop.
// MODE 0: t = g_h @ W1 + b1, write g_t, accumulate column sum/sumsq
// MODE 1: out = relu(t*A + B) @ W2 + b2, BN affine computed from g_sum/g_sq
// ---------------------------------------------------------------------------
#define TILE_R    128
#define IN_STRIDE 132
#define SMEM_FLOATS (DIM * DIM + DIM * IN_STRIDE + 2 * DIM)   // 12672

template <int MODE>
__global__ void gemm_kernel(const float* __restrict__ W, const float* __restrict__ bias,
                            const float* __restrict__ gamma, const float* __restrict__ beta,
                            float* __restrict__ out_ext) {
    extern __shared__ float sm[];
    float* sW   = sm;                               // [64][64]
    float* sIn  = sm + DIM * DIM;                   // [64][IN_STRIDE] k-major
    float* sAff = sm + DIM * DIM + DIM * IN_STRIDE; // [2][64]

    const float* in  = (MODE == 0) ? g_h : g_t;
    float*       out = (MODE == 0) ? g_t : out_ext;

    int t  = threadIdx.x;            // 128 threads
    int r0 = blockIdx.x * TILE_R;

    #pragma unroll
    for (int i = 0; i < 8; i++)
        ((float4*)sW)[t + i * 128] = ((const float4*)W)[t + i * 128];

    if (MODE == 1) {
        if (t < DIM) {
            const float inv = 1.0f / (float)N_NODES;
            float mu  = g_sum[t] * inv;
            float var = g_sq[t] * inv - mu * mu;
            float a   = gamma[t] * rsqrtf(var + 1e-5f);
            sAff[t]       = a;
            sAff[DIM + t] = fmaf(-mu, a, beta[t]);
        }
        __syncthreads();
    }

    {
        int row = r0 + t;
        bool valid = row < N_NODES;
        const float4* rp = (const float4*)(in + (size_t)row * DIM);
        #pragma unroll
        for (int q = 0; q < 16; q++) {
            float4 v = valid ? __ldg(rp + q) : make_float4(0.f, 0.f, 0.f, 0.f);
            int k0 = q * 4;
            if (MODE == 1) {
                v.x = fmaxf(fmaf(v.x, sAff[k0 + 0], sAff[DIM + k0 + 0]), 0.0f);
                v.y = fmaxf(fmaf(v.y, sAff[k0 + 1], sAff[DIM + k0 + 1]), 0.0f);
                v.z = fmaxf(fmaf(v.z, sAff[k0 + 2], sAff[DIM + k0 + 2]), 0.0f);
                v.w = fmaxf(fmaf(v.w, sAff[k0 + 3], sAff[DIM + k0 + 3]), 0.0f);
            }
            sIn[(k0 + 0) * IN_STRIDE + t] = v.x;
            sIn[(k0 + 1) * IN_STRIDE + t] = v.y;
            sIn[(k0 + 2) * IN_STRIDE + t] = v.z;
            sIn[(k0 + 3) * IN_STRIDE + t] = v.w;
        }
    }
    __syncthreads();

    int rg = t >> 3;  // 0..15
    int cg = t & 7;   // 0..7

    unsigned long long acc2[8][4];
    #pragma unroll
    for (int i = 0; i < 8; i++)
        #pragma unroll
        for (int jp = 0; jp < 4; jp++) acc2[i][jp] = 0ull;

    #pragma unroll 2
    for (int k = 0; k < 64; k++) {
        float4 a0 = *(const float4*)(sIn + k * IN_STRIDE + rg * 8);
        float4 a1 = *(const float4*)(sIn + k * IN_STRIDE + rg * 8 + 4);
        float4 w0 = *(const float4*)(sW  + k * DIM + cg * 8);
        float4 w1 = *(const float4*)(sW  + k * DIM + cg * 8 + 4);
        unsigned long long w2[4];
        PACK2(w2[0], w0.x, w0.y);
        PACK2(w2[1], w0.z, w0.w);
        PACK2(w2[2], w1.x, w1.y);
        PACK2(w2[3], w1.z, w1.w);
        float av[8] = {a0.x, a0.y, a0.z, a0.w, a1.x, a1.y, a1.z, a1.w};
        #pragma unroll
        for (int i = 0; i < 8; i++) {
            unsigned long long ai;
            PACK2(ai, av[i], av[i]);
            #pragma unroll
            for (int jp = 0; jp < 4; jp++)
                FMA2(acc2[i][jp], ai, w2[jp]);
        }
    }

    float bs[8];
    #pragma unroll
    for (int j = 0; j < 8; j++) bs[j] = bias[cg * 8 + j];

    float csum[8], csq[8];
    #pragma unroll
    for (int j = 0; j < 8; j++) { csum[j] = 0.0f; csq[j] = 0.0f; }

    #pragma unroll
    for (int i = 0; i < 8; i++) {
        int row = r0 + rg * 8 + i;
        if (row < N_NODES) {
            float v[8];
            #pragma unroll
            for (int jp = 0; jp < 4; jp++) {
                float lo, hi;
                UNPACK2(lo, hi, acc2[i][jp]);
                v[2 * jp]     = lo + bs[2 * jp];
                v[2 * jp + 1] = hi + bs[2 * jp + 1];
            }
            if (MODE == 0) {
                #pragma unroll
                for (int j = 0; j < 8; j++) { csum[j] += v[j]; csq[j] += v[j] * v[j]; }
            }
            *(float4*)(out + (size_t)row * DIM + cg * 8)     = make_float4(v[0], v[1], v[2], v[3]);
            *(float4*)(out + (size_t)row * DIM + cg * 8 + 4) = make_float4(v[4], v[5], v[6], v[7]);
        }
    }

    if (MODE == 0) {
        __syncthreads();
        float* red = sIn;
        #pragma unroll
        for (int j = 0; j < 8; j++) {
            red[rg * 64 + cg * 8 + j]        = csum[j];
            red[(16 + rg) * 64 + cg * 8 + j] = csq[j];
        }
        __syncthreads();
        if (t < 64) {
            float s = 0.0f;
            #pragma unroll
            for (int g = 0; g < 16; g++) s += red[g * 64 + t];
            atomicAdd(&g_sum[t], s);
        } else {
            int c = t - 64;
            float s = 0.0f;
            #pragma unroll
            for (int g = 0; g < 16; g++) s += red[(16 + g) * 64 + c];
            atomicAdd(&g_sq[c], s);
        }
    }
}

// ---------------------------------------------------------------------------
extern "C" void kernel_launch(void* const* d_in, const int* in_sizes, int n_in,
                              void* d_out, int out_size) {
    const float* x     = (const float*)d_in[0];
    const float* emb   = (const float*)d_in[1];
    const float* eps   = (const float*)d_in[2];
    const float* W1    = (const float*)d_in[3];
    const float* b1    = (const float*)d_in[4];
    const float* gamma = (const float*)d_in[5];
    const float* beta  = (const float*)d_in[6];
    const float* W2    = (const float*)d_in[7];
    const float* b2    = (const float*)d_in[8];
    const int*   ei    = (const int*)d_in[9];
    const int*   ea    = (const int*)d_in[10];
    float*       out   = (float*)d_out;

    const int smem_bytes = SMEM_FLOATS * 4;  // 50688 > 48K: opt in
    cudaFuncSetAttribute(gemm_kernel<0>, cudaFuncAttributeMaxDynamicSharedMemorySize, smem_bytes);
    cudaFuncSetAttribute(gemm_kernel<1>, cudaFuncAttributeMaxDynamicSharedMemorySize, smem_bytes);

    prephist_kernel<<<(N_NODES * DIM / 8 + 255) / 256, 256>>>(x, ei);   // 3125 blocks
    scan_kernel<<<NCH, SCAN_CHUNK>>>();
    scatter_kernel<<<(N_EDGES / 4 + 255) / 256, 256>>>(ei, ea);         // 1563 blocks
    agg_kernel<<<(N_NODES * 8 + 255) / 256, 256>>>(x, emb, eps);        // 3125 blocks
    const int gblocks = (N_NODES + TILE_R - 1) / TILE_R;                // 782
    gemm_kernel<0><<<gblocks, 128, smem_bytes>>>(W1, b1, nullptr, nullptr, nullptr);
    gemm_kernel<1><<<gblocks, 128, smem_bytes>>>(W2, b2, gamma, beta, out);
}